// round 1
// baseline (speedup 1.0000x reference)
#include <cuda_runtime.h>
#include <math.h>

#define PTS        4096
#define BATCH      32
#define TPB        256
#define TILES      (PTS / TPB)          // 16 blocks per batch per pass
#define BLOCKS_PER_PASS (BATCH * TILES) // 512
#define SMEM_BYTES (PTS * sizeof(float4))

// Scratch for block partial sums: 2 passes x 512 blocks. Every slot is
// written on every launch, so no zero-init needed (deterministic).
__device__ float g_partial[2 * BLOCKS_PER_PASS];

// For each query point in A (one per thread), find min distance to the full
// target set B (staged in smem as float4 {x,y,z,|g|^2}), then block-reduce
// the sum of sqrt(min d2) into g_partial[partial_offset + block].
__global__ __launch_bounds__(TPB) void chamfer_pass_kernel(
    const float* __restrict__ Aq,   // query points  [B, PTS, 3]
    const float* __restrict__ Bt,   // target points [B, PTS, 3]
    int partial_offset)
{
    extern __shared__ float4 s[];   // PTS float4 = 64 KB

    const int b    = blockIdx.y;
    const int tile = blockIdx.x;

    // Cooperative stage of the full target set for this batch.
    const float* __restrict__ Bb = Bt + (size_t)b * PTS * 3;
    for (int i = threadIdx.x; i < PTS; i += TPB) {
        float x = Bb[3 * i + 0];
        float y = Bb[3 * i + 1];
        float z = Bb[3 * i + 2];
        s[i] = make_float4(x, y, z, fmaf(x, x, fmaf(y, y, z * z)));
    }
    __syncthreads();

    // This thread's query point.
    const int n = tile * TPB + threadIdx.x;
    const float* __restrict__ a = Aq + ((size_t)b * PTS + n) * 3;
    const float px = a[0], py = a[1], pz = a[2];
    const float p2 = fmaf(px, px, fmaf(py, py, pz * pz));

    // min_m (g2 - 2<p,g>)  -- p2 added after the loop (constant per thread).
    // 4 independent accumulators break the FMNMX dependency chain.
    float best0 = 3.0e38f, best1 = 3.0e38f, best2 = 3.0e38f, best3 = 3.0e38f;

    #pragma unroll 2
    for (int m = 0; m < PTS; m += 4) {
        float4 g0 = s[m + 0];
        float4 g1 = s[m + 1];
        float4 g2 = s[m + 2];
        float4 g3 = s[m + 3];

        float c0 = fmaf(px, g0.x, fmaf(py, g0.y, pz * g0.z));
        float c1 = fmaf(px, g1.x, fmaf(py, g1.y, pz * g1.z));
        float c2 = fmaf(px, g2.x, fmaf(py, g2.y, pz * g2.z));
        float c3 = fmaf(px, g3.x, fmaf(py, g3.y, pz * g3.z));

        float t0 = fmaf(-2.0f, c0, g0.w);
        float t1 = fmaf(-2.0f, c1, g1.w);
        float t2 = fmaf(-2.0f, c2, g2.w);
        float t3 = fmaf(-2.0f, c3, g3.w);

        best0 = fminf(best0, t0);
        best1 = fminf(best1, t1);
        best2 = fminf(best2, t2);
        best3 = fminf(best3, t3);
    }

    float best = fminf(fminf(best0, best1), fminf(best2, best3));
    float d2   = best + p2;
    float dist = sqrtf(fmaxf(d2, 1e-12f));

    // Block reduction: sum of dist over TPB threads.
    const unsigned FULL = 0xFFFFFFFFu;
    #pragma unroll
    for (int o = 16; o > 0; o >>= 1)
        dist += __shfl_down_sync(FULL, dist, o);

    __shared__ float wsum[TPB / 32];
    const int lane = threadIdx.x & 31;
    const int wid  = threadIdx.x >> 5;
    if (lane == 0) wsum[wid] = dist;
    __syncthreads();

    if (threadIdx.x < TPB / 32) {
        float v = wsum[threadIdx.x];
        #pragma unroll
        for (int o = (TPB / 32) / 2; o > 0; o >>= 1)
            v += __shfl_down_sync(FULL, v, o, TPB / 32);
        if (threadIdx.x == 0)
            g_partial[partial_offset + b * TILES + tile] = v;
    }
}

// Reduce 1024 partials -> scalar mean. One block, 1024 threads.
__global__ void chamfer_finalize_kernel(float* __restrict__ out)
{
    float v = g_partial[threadIdx.x];
    const unsigned FULL = 0xFFFFFFFFu;
    #pragma unroll
    for (int o = 16; o > 0; o >>= 1)
        v += __shfl_down_sync(FULL, v, o);

    __shared__ float wsum[32];
    const int lane = threadIdx.x & 31;
    const int wid  = threadIdx.x >> 5;
    if (lane == 0) wsum[wid] = v;
    __syncthreads();

    if (threadIdx.x < 32) {
        float t = wsum[threadIdx.x];
        #pragma unroll
        for (int o = 16; o > 0; o >>= 1)
            t += __shfl_down_sync(FULL, t, o);
        if (threadIdx.x == 0)
            out[0] = t * (1.0f / (float)(BATCH * PTS));
    }
}

extern "C" void kernel_launch(void* const* d_in, const int* in_sizes, int n_in,
                              void* d_out, int out_size)
{
    (void)in_sizes; (void)n_in; (void)out_size;
    const float* pred = (const float*)d_in[0];
    const float* gt   = (const float*)d_in[1];
    float* out        = (float*)d_out;

    cudaFuncSetAttribute(chamfer_pass_kernel,
                         cudaFuncAttributeMaxDynamicSharedMemorySize, SMEM_BYTES);

    dim3 grid(TILES, BATCH);

    // chamfer1 = mean over gt points of min over pred:   query = gt, target = pred
    chamfer_pass_kernel<<<grid, TPB, SMEM_BYTES>>>(gt, pred, 0);
    // chamfer2 = mean over pred points of min over gt:   query = pred, target = gt
    chamfer_pass_kernel<<<grid, TPB, SMEM_BYTES>>>(pred, gt, BLOCKS_PER_PASS);

    chamfer_finalize_kernel<<<1, 2 * BLOCKS_PER_PASS>>>(out);
}

// round 2
// speedup vs baseline: 2.1586x; 2.1586x over previous
#include <cuda_runtime.h>
#include <math.h>

#define PTS      4096
#define BATCH    32
#define TPB      256
#define Q        4                       // queries per thread
#define TILE_Q   (TPB * Q)               // 1024 queries per block
#define TILES    (PTS / TILE_Q)          // 4
#define NPART    (2 * BATCH * TILES)     // 256 block partials
#define SMEM_BYTES (PTS * 16)            // 4096 points * 16B packed = 64KB

__device__ float g_partial[NPART];

// ---- Blackwell packed f32x2 helpers ----------------------------------------
__device__ __forceinline__ unsigned long long splat2(float v) {
    unsigned long long r;
    asm("mov.b64 %0, {%1, %1};" : "=l"(r) : "f"(v));
    return r;
}
__device__ __forceinline__ unsigned long long fma2(unsigned long long a,
                                                   unsigned long long b,
                                                   unsigned long long c) {
    unsigned long long d;
    asm("fma.rn.f32x2 %0, %1, %2, %3;" : "=l"(d) : "l"(a), "l"(b), "l"(c));
    return d;
}
// Unpack (free: register-pair rename) and fold into two scalar min accumulators.
__device__ __forceinline__ void min2_acc(unsigned long long t, float& a0, float& a1) {
    float lo, hi;
    asm("mov.b64 {%0, %1}, %2;" : "=f"(lo), "=f"(hi) : "l"(t));
    a0 = fminf(a0, lo);
    a1 = fminf(a1, hi);
}

// One fused kernel: blockIdx.z = direction (0: query=gt/target=pred, 1: reverse).
// Target set staged in smem as packed pairs: for pair j (targets 2j, 2j+1):
//   float4 @ 2j:   { -2*x0, -2*x1, -2*y0, -2*y1 }
//   float4 @ 2j+1: { -2*z0, -2*z1,  g2_0,  g2_1 }
// so each u64 lane-pair holds two targets, and
//   d2 - p2 = fma2(qz, zz, fma2(qy, yy, fma2(qx, xx, gg)))   (3 FFMA2 / 2 targets)
__global__ __launch_bounds__(TPB) void chamfer_fused_kernel(
    const float* __restrict__ pred,
    const float* __restrict__ gt)
{
    extern __shared__ float4 sf[];

    const int b    = blockIdx.y;
    const int tile = blockIdx.x;
    const int dir  = blockIdx.z;

    const float* __restrict__ Aq = dir ? pred : gt;   // queries
    const float* __restrict__ Bt = dir ? gt   : pred; // targets

    // ---- Stage packed target pairs -----------------------------------------
    const float* __restrict__ Bb = Bt + (size_t)b * PTS * 3;
    for (int j = threadIdx.x; j < PTS / 2; j += TPB) {
        const float* p = Bb + 6 * j;
        float x0 = p[0], y0 = p[1], z0 = p[2];
        float x1 = p[3], y1 = p[4], z1 = p[5];
        float g0 = fmaf(x0, x0, fmaf(y0, y0, z0 * z0));
        float g1 = fmaf(x1, x1, fmaf(y1, y1, z1 * z1));
        sf[2 * j]     = make_float4(-2.0f * x0, -2.0f * x1, -2.0f * y0, -2.0f * y1);
        sf[2 * j + 1] = make_float4(-2.0f * z0, -2.0f * z1, g0, g1);
    }
    __syncthreads();

    // ---- Load Q query points, splat coords once ----------------------------
    unsigned long long qx[Q], qy[Q], qz[Q];
    float p2[Q];
    #pragma unroll
    for (int q = 0; q < Q; q++) {
        const int n = tile * TILE_Q + q * TPB + threadIdx.x;  // coalesced-ish
        const float* a = Aq + ((size_t)b * PTS + n) * 3;
        float x = a[0], y = a[1], z = a[2];
        qx[q] = splat2(x);
        qy[q] = splat2(y);
        qz[q] = splat2(z);
        p2[q] = fmaf(x, x, fmaf(y, y, z * z));
    }

    // ---- Main loop: 2 targets per iteration, Q queries each ----------------
    float acc0[Q], acc1[Q];
    #pragma unroll
    for (int q = 0; q < Q; q++) { acc0[q] = 3.0e38f; acc1[q] = 3.0e38f; }

    const ulonglong2* __restrict__ sp = (const ulonglong2*)sf;
    #pragma unroll 4
    for (int j = 0; j < PTS / 2; j++) {
        ulonglong2 u0 = sp[2 * j];       // {xx, yy}
        ulonglong2 u1 = sp[2 * j + 1];   // {zz, gg}
        #pragma unroll
        for (int q = 0; q < Q; q++) {
            unsigned long long t =
                fma2(qz[q], u1.x, fma2(qy[q], u0.y, fma2(qx[q], u0.x, u1.y)));
            min2_acc(t, acc0[q], acc1[q]);
        }
    }

    // ---- Epilogue: sqrt per query, sum over this thread's Q queries --------
    float tsum = 0.0f;
    #pragma unroll
    for (int q = 0; q < Q; q++) {
        float best = fminf(acc0[q], acc1[q]) + p2[q];
        tsum += sqrtf(fmaxf(best, 1e-12f));
    }

    // ---- Block reduction ---------------------------------------------------
    const unsigned FULL = 0xFFFFFFFFu;
    #pragma unroll
    for (int o = 16; o > 0; o >>= 1)
        tsum += __shfl_down_sync(FULL, tsum, o);

    __shared__ float wsum[TPB / 32];
    const int lane = threadIdx.x & 31;
    const int wid  = threadIdx.x >> 5;
    if (lane == 0) wsum[wid] = tsum;
    __syncthreads();

    if (threadIdx.x < TPB / 32) {
        float v = wsum[threadIdx.x];
        #pragma unroll
        for (int o = (TPB / 32) / 2; o > 0; o >>= 1)
            v += __shfl_down_sync(FULL, v, o, TPB / 32);
        if (threadIdx.x == 0)
            g_partial[(dir * BATCH + b) * TILES + tile] = v;
    }
}

// Reduce NPART partials -> scalar mean. One block of NPART threads.
__global__ void chamfer_finalize_kernel(float* __restrict__ out)
{
    float v = g_partial[threadIdx.x];
    const unsigned FULL = 0xFFFFFFFFu;
    #pragma unroll
    for (int o = 16; o > 0; o >>= 1)
        v += __shfl_down_sync(FULL, v, o);

    __shared__ float wsum[NPART / 32];
    const int lane = threadIdx.x & 31;
    const int wid  = threadIdx.x >> 5;
    if (lane == 0) wsum[wid] = v;
    __syncthreads();

    if (threadIdx.x < NPART / 32) {
        float t = wsum[threadIdx.x];
        #pragma unroll
        for (int o = (NPART / 32) / 2; o > 0; o >>= 1)
            t += __shfl_down_sync(FULL, t, o, NPART / 32);
        if (threadIdx.x == 0)
            out[0] = t * (1.0f / (float)(BATCH * PTS));
    }
}

extern "C" void kernel_launch(void* const* d_in, const int* in_sizes, int n_in,
                              void* d_out, int out_size)
{
    (void)in_sizes; (void)n_in; (void)out_size;
    const float* pred = (const float*)d_in[0];
    const float* gt   = (const float*)d_in[1];
    float* out        = (float*)d_out;

    cudaFuncSetAttribute(chamfer_fused_kernel,
                         cudaFuncAttributeMaxDynamicSharedMemorySize, SMEM_BYTES);

    dim3 grid(TILES, BATCH, 2);
    chamfer_fused_kernel<<<grid, TPB, SMEM_BYTES>>>(pred, gt);
    chamfer_finalize_kernel<<<1, NPART>>>(out);
}